// round 2
// baseline (speedup 1.0000x reference)
#include <cuda_runtime.h>

typedef unsigned long long ull_t;

#define D      64
#define H      128
#define GDIM   64
#define NMAX   100000
#define WARPS  8
#define EPW    8

// ---------- packed fp32x2 helpers (Blackwell FFMA2 path) ----------
static __device__ __forceinline__ ull_t ffma2(ull_t a, ull_t b, ull_t c) {
    ull_t d;
    asm("fma.rn.f32x2 %0, %1, %2, %3;" : "=l"(d) : "l"(a), "l"(b), "l"(c));
    return d;
}
static __device__ __forceinline__ ull_t fadd2(ull_t a, ull_t b) {
    ull_t d;
    asm("add.rn.f32x2 %0, %1, %2;" : "=l"(d) : "l"(a), "l"(b));
    return d;
}
static __device__ __forceinline__ ull_t pack2(float lo, float hi) {
    ull_t r;
    asm("mov.b64 %0, {%1, %2};" : "=l"(r) : "f"(lo), "f"(hi));
    return r;
}
static __device__ __forceinline__ void unpack2(ull_t v, float& lo, float& hi) {
    asm("mov.b64 {%0, %1}, %2;" : "=f"(lo), "=f"(hi) : "l"(v));
}

// ---------- device scratch (allocation-free contract) ----------
__device__ float g_P[(size_t)NMAX * H];   // x @ W1[64:128]   (receiver block)
__device__ float g_Q[(size_t)NMAX * H];   // x @ W1[128:192] + R[batch[n]]  (sender+global+b1)
__device__ float g_R[GDIM * H];           // u @ W1[192:256] + b1

// ================= R = u @ W1_glob + b1 =================
__global__ void k_preR(const float* __restrict__ u,
                       const float* __restrict__ W1,
                       const float* __restrict__ b1) {
    __shared__ float us[D];
    int g = blockIdx.x;
    int j = threadIdx.x;          // 0..127
    if (j < D) us[j] = u[g * D + j];
    __syncthreads();
    float acc = b1[j];
#pragma unroll 8
    for (int k = 0; k < D; k++)
        acc += us[k] * W1[(192 + k) * H + j];
    g_R[g * H + j] = acc;
}

// ================= P, Q' node projections =================
__global__ void k_prePQ(const float* __restrict__ x,
                        const float* __restrict__ W1,
                        const int* __restrict__ batch,
                        int N) {
    __shared__ __align__(16) float xs[8][D];
    int t = threadIdx.x;
    int base = blockIdx.x * 8;

    {
        int nn = base + (t >> 4);
        int part = t & 15;
        if (nn >= N) nn = N - 1;
        ((float4*)&xs[0][0])[t] = ((const float4*)x)[(size_t)nn * 16 + part];
    }
    __syncthreads();

    int  jp  = t & 63;
    bool isQ = (t >= 64);
    const float* W = W1 + (isQ ? 128 : 64) * H + 2 * jp;

    ull_t acc[8];
#pragma unroll
    for (int m = 0; m < 8; m++) acc[m] = pack2(0.0f, 0.0f);

#pragma unroll 4
    for (int k = 0; k < D; k += 2) {
        ull_t w0 = *(const ull_t*)(W + (size_t)k * H);
        ull_t w1 = *(const ull_t*)(W + (size_t)(k + 1) * H);
#pragma unroll
        for (int m = 0; m < 8; m++) {
            ull_t xv = *(const ull_t*)&xs[m][k];
            float x0, x1;
            unpack2(xv, x0, x1);
            acc[m] = ffma2(pack2(x0, x0), w0, acc[m]);
            acc[m] = ffma2(pack2(x1, x1), w1, acc[m]);
        }
    }

    float* dst = isQ ? g_Q : g_P;
#pragma unroll
    for (int m = 0; m < 8; m++) {
        int n = base + m;
        if (n >= N) break;
        ull_t v = acc[m];
        if (isQ) {
            int bg = batch[n];
            v = fadd2(v, *(const ull_t*)(g_R + bg * H + 2 * jp));
        }
        *(ull_t*)(dst + (size_t)n * H + 2 * jp) = v;
    }
}

// ================= edge kernel =================
__global__ __launch_bounds__(256, 1) void k_edge(
    const float* __restrict__ e,
    const float* __restrict__ W1,
    const float* __restrict__ W2,
    const float* __restrict__ b2,
    const float* __restrict__ ln_g,
    const float* __restrict__ ln_b,
    const int* __restrict__ eidx,
    float* __restrict__ out,
    int E) {
    extern __shared__ float smem[];
    float* As  = smem;                 // 64*128 f
    float* W2s = As + D * H;           // 128*128 f
    float* stg = W2s + H * H;          // WARPS*EPW*256 f

    int tid = threadIdx.x;
#pragma unroll 4
    for (int i = tid; i < D * H / 4; i += 256)
        ((float4*)As)[i] = ((const float4*)W1)[i];
#pragma unroll 4
    for (int i = tid; i < H * H / 4; i += 256)
        ((float4*)W2s)[i] = ((const float4*)W2)[i];
    __syncthreads();

    int warp = tid >> 5, lane = tid & 31;
    float* wsd = stg + warp * (EPW * 256);

    ull_t b2p0 = *(const ull_t*)(b2 + 2 * lane);
    ull_t b2p1 = *(const ull_t*)(b2 + D + 2 * lane);
    float lg0 = ln_g[2 * lane],      lg1 = ln_g[2 * lane + 1];
    float lg2 = ln_g[64 + 2 * lane], lg3 = ln_g[64 + 2 * lane + 1];
    float lb0 = ln_b[2 * lane],      lb1 = ln_b[2 * lane + 1];
    float lb2 = ln_b[64 + 2 * lane], lb3 = ln_b[64 + 2 * lane + 1];

    int ngroups = (E + EPW - 1) / EPW;

    for (int grp = blockIdx.x * WARPS + warp; grp < ngroups;
         grp += gridDim.x * WARPS) {
        int i0 = grp * EPW;
        __syncwarp();

        int rowm = 0, colm = 0;
        if (lane < EPW) {
            int ee = i0 + lane;
            int ec = ee < E ? ee : E - 1;
            rowm = eidx[ec];
            colm = eidx[(size_t)E + ec];
        }

        ull_t acc0[EPW], acc1[EPW];
#pragma unroll
        for (int m = 0; m < EPW; m++) {
            int r = __shfl_sync(0xffffffffu, rowm, m);
            int c = __shfl_sync(0xffffffffu, colm, m);
            int im = i0 + m;
            int ic = im < E ? im : E - 1;
            float2 v = ((const float2*)e)[(size_t)ic * 32 + lane];
            *(float4*)(wsd + m * 256 + 4 * lane) =
                make_float4(v.x, v.x, v.y, v.y);
            ull_t p0 = *(const ull_t*)(g_P + (size_t)c * H + 2 * lane);
            ull_t q0 = *(const ull_t*)(g_Q + (size_t)r * H + 2 * lane);
            ull_t p1 = *(const ull_t*)(g_P + (size_t)c * H + D + 2 * lane);
            ull_t q1 = *(const ull_t*)(g_Q + (size_t)r * H + D + 2 * lane);
            acc0[m] = fadd2(p0, q0);
            acc1[m] = fadd2(p1, q1);
        }
        __syncwarp();

        // ---------------- GEMM1: acc += e @ A   (K = 64) ----------------
#pragma unroll 2
        for (int k = 0; k < D; k += 4) {
            ull_t w0a = *(const ull_t*)(As + (k + 0) * H + 2 * lane);
            ull_t w0b = *(const ull_t*)(As + (k + 0) * H + 64 + 2 * lane);
            ull_t w1a = *(const ull_t*)(As + (k + 1) * H + 2 * lane);
            ull_t w1b = *(const ull_t*)(As + (k + 1) * H + 64 + 2 * lane);
            ull_t w2a = *(const ull_t*)(As + (k + 2) * H + 2 * lane);
            ull_t w2b = *(const ull_t*)(As + (k + 2) * H + 64 + 2 * lane);
            ull_t w3a = *(const ull_t*)(As + (k + 3) * H + 2 * lane);
            ull_t w3b = *(const ull_t*)(As + (k + 3) * H + 64 + 2 * lane);
#pragma unroll
            for (int m = 0; m < EPW; m++) {
                const float4* dp = (const float4*)(wsd + m * 256 + 2 * k);
                float4 d0 = dp[0];
                float4 d1 = dp[1];
                ull_t e0 = pack2(d0.x, d0.y);
                ull_t e1 = pack2(d0.z, d0.w);
                ull_t e2 = pack2(d1.x, d1.y);
                ull_t e3 = pack2(d1.z, d1.w);
                acc0[m] = ffma2(e0, w0a, acc0[m]);
                acc1[m] = ffma2(e0, w0b, acc1[m]);
                acc0[m] = ffma2(e1, w1a, acc0[m]);
                acc1[m] = ffma2(e1, w1b, acc1[m]);
                acc0[m] = ffma2(e2, w2a, acc0[m]);
                acc1[m] = ffma2(e2, w2b, acc1[m]);
                acc0[m] = ffma2(e3, w3a, acc0[m]);
                acc1[m] = ffma2(e3, w3b, acc1[m]);
            }
        }
        __syncwarp();

        // relu + restage h1 duplicated
#pragma unroll
        for (int m = 0; m < EPW; m++) {
            float a0, a1, a2, a3;
            unpack2(acc0[m], a0, a1);
            unpack2(acc1[m], a2, a3);
            a0 = fmaxf(a0, 0.0f); a1 = fmaxf(a1, 0.0f);
            a2 = fmaxf(a2, 0.0f); a3 = fmaxf(a3, 0.0f);
            *(float4*)(wsd + m * 256 + 4 * lane) =
                make_float4(a0, a0, a1, a1);
            *(float4*)(wsd + m * 256 + 128 + 4 * lane) =
                make_float4(a2, a2, a3, a3);
        }
        __syncwarp();

#pragma unroll
        for (int m = 0; m < EPW; m++) { acc0[m] = b2p0; acc1[m] = b2p1; }

        // ---------------- GEMM2: acc += h1 @ W2  (K = 128) ----------------
#pragma unroll 2
        for (int k = 0; k < H; k += 4) {
            ull_t w0a = *(const ull_t*)(W2s + (k + 0) * H + 2 * lane);
            ull_t w0b = *(const ull_t*)(W2s + (k + 0) * H + 64 + 2 * lane);
            ull_t w1a = *(const ull_t*)(W2s + (k + 1) * H + 2 * lane);
            ull_t w1b = *(const ull_t*)(W2s + (k + 1) * H + 64 + 2 * lane);
            ull_t w2a = *(const ull_t*)(W2s + (k + 2) * H + 2 * lane);
            ull_t w2b = *(const ull_t*)(W2s + (k + 2) * H + 64 + 2 * lane);
            ull_t w3a = *(const ull_t*)(W2s + (k + 3) * H + 2 * lane);
            ull_t w3b = *(const ull_t*)(W2s + (k + 3) * H + 64 + 2 * lane);
#pragma unroll
            for (int m = 0; m < EPW; m++) {
                const float4* dp = (const float4*)(wsd + m * 256 + 2 * k);
                float4 d0 = dp[0];
                float4 d1 = dp[1];
                ull_t e0 = pack2(d0.x, d0.y);
                ull_t e1 = pack2(d0.z, d0.w);
                ull_t e2 = pack2(d1.x, d1.y);
                ull_t e3 = pack2(d1.z, d1.w);
                acc0[m] = ffma2(e0, w0a, acc0[m]);
                acc1[m] = ffma2(e0, w0b, acc1[m]);
                acc0[m] = ffma2(e1, w1a, acc0[m]);
                acc1[m] = ffma2(e1, w1b, acc1[m]);
                acc0[m] = ffma2(e2, w2a, acc0[m]);
                acc1[m] = ffma2(e2, w2b, acc1[m]);
                acc0[m] = ffma2(e3, w3a, acc0[m]);
                acc1[m] = ffma2(e3, w3b, acc1[m]);
            }
        }

        // ---------------- relu + LayerNorm + store ----------------
#pragma unroll
        for (int m = 0; m < EPW; m++) {
            int im = i0 + m;
            float a0, a1, a2, a3;
            unpack2(acc0[m], a0, a1);
            unpack2(acc1[m], a2, a3);
            a0 = fmaxf(a0, 0.0f); a1 = fmaxf(a1, 0.0f);
            a2 = fmaxf(a2, 0.0f); a3 = fmaxf(a3, 0.0f);
            float s  = a0 + a1 + a2 + a3;
            float sq = a0 * a0 + a1 * a1 + a2 * a2 + a3 * a3;
#pragma unroll
            for (int off = 16; off; off >>= 1) {
                s  += __shfl_xor_sync(0xffffffffu, s,  off);
                sq += __shfl_xor_sync(0xffffffffu, sq, off);
            }
            float mean = s * (1.0f / H);
            float var  = sq * (1.0f / H) - mean * mean;
            float rstd = rsqrtf(var + 1e-5f);
            float y0 = (a0 - mean) * rstd * lg0 + lb0;
            float y1 = (a1 - mean) * rstd * lg1 + lb1;
            float y2 = (a2 - mean) * rstd * lg2 + lb2;
            float y3 = (a3 - mean) * rstd * lg3 + lb3;
            if (im < E) {
                float2* o = (float2*)(out + (size_t)im * H);
                o[lane]      = make_float2(y0, y1);
                o[32 + lane] = make_float2(y2, y3);
            }
        }
    }
}

// ================= launch =================
extern "C" void kernel_launch(void* const* d_in, const int* in_sizes, int n_in,
                              void* d_out, int out_size) {
    const float* x     = (const float*)d_in[0];
    const float* e     = (const float*)d_in[1];
    const float* u     = (const float*)d_in[2];
    const float* W1    = (const float*)d_in[3];
    const float* b1    = (const float*)d_in[4];
    const float* W2    = (const float*)d_in[5];
    const float* b2    = (const float*)d_in[6];
    const float* ln_g  = (const float*)d_in[7];
    const float* ln_b  = (const float*)d_in[8];
    const int*   eidx  = (const int*)d_in[9];    // int32 on device (JAX x64 disabled)
    const int*   batch = (const int*)d_in[10];   // int32 on device
    float*       out   = (float*)d_out;

    int N = in_sizes[0] / D;   // 100000
    int E = in_sizes[1] / D;   // 1000000

    const int SMEM_EDGE = (D * H + H * H + WARPS * EPW * 256) * (int)sizeof(float); // 160 KB
    cudaFuncSetAttribute(k_edge, cudaFuncAttributeMaxDynamicSharedMemorySize, SMEM_EDGE);

    k_preR<<<GDIM, H>>>(u, W1, b1);
    k_prePQ<<<(N + 7) / 8, 128>>>(x, W1, batch, N);
    k_edge<<<304, 256, SMEM_EDGE>>>(e, W1, W2, b2, ln_g, ln_b, eidx, out, E);
}